// round 9
// baseline (speedup 1.0000x reference)
#include <cuda_runtime.h>
#include <cstdint>
#include <cstddef>

typedef unsigned long long u64;

// ---------------------------------------------------------------------------
// Shapes: B=4, SQ=2048, SK=1024, D=1024. All GEMM K = 1024.
// ---------------------------------------------------------------------------

// scratch (device globals; allocation forbidden)
__device__ __align__(256) float g_k  [4ull * 1024 * 1024];   // k  [b*1024+s][d]
__device__ __align__(256) float g_vt [1024ull * 4096];       // vT [d][b*1024+s]
__device__ __align__(256) float g_qy [8192ull * 1024];       // qy
__device__ __align__(256) float g_inv[8192ull * 1024];       // inv
__device__ __align__(256) float g_qk [8192ull * 1024];       // qk / attn

__device__ __forceinline__ u64 pack_dup(float a) {
    u64 r;
    asm("mov.b64 %0, {%1, %1};" : "=l"(r) : "f"(a));
    return r;
}
__device__ __forceinline__ void fma2(u64 &d, u64 a, u64 b) {
    asm("fma.rn.f32x2 %0, %1, %2, %0;" : "+l"(d) : "l"(a), "l"(b));
}

#define RSA 264                  // A smem row stride (floats, duplicated row)
#define RSB 132                  // B smem row stride (floats)
#define ABUF (8 * RSA)           // one A slab
#define BBUF (8 * RSB)           // one B slab

// ---------------------------------------------------------------------------
// Core: C[m0+128, n0+128] = sum_k A[m,k] * B[n,k]  (NT), fp32, K=1024.
// 256 threads; thread (tx=tid&15, ty=tid>>4) owns rows m0+8ty..+7 and
// cols {n0+4tx..+3} u {n0+64+4tx..+3}. acc u64-packed f32x2 (FFMA2).
// A stored duplicated in smem ([k][2m]=[k][2m+1]); B row-major [k][n].
// K-slab 8, 2-stage LDG prefetch, one barrier per slab.
// epi: 0 = +bias[n] | 1 = +bias[m] | 2 = /= aux[r*ldC+col] | 3 = none
// ---------------------------------------------------------------------------
__device__ __forceinline__ void run_gemm(
    const float* __restrict__ A, int ldA,
    const float* __restrict__ B, int ldB,
    float* __restrict__ C, int ldC,
    const float* __restrict__ aux, int epi,
    int m0, int n0, float* sA, float* sB)
{
    const int tid = threadIdx.x;
    const int tx  = tid & 15, ty = tid >> 4;
    const int row = tid >> 1, ks = (tid & 1) * 4;

    const float* Ag = A + (size_t)(m0 + row) * ldA + ks;
    const float* Bg = B + (size_t)(n0 + row) * ldB + ks;

    u64 acc[8][4];
    #pragma unroll
    for (int i = 0; i < 8; i++)
        #pragma unroll
        for (int j = 0; j < 4; j++) acc[i][j] = 0ull;

    float4 ra = *(const float4*)Ag;
    float4 rb = *(const float4*)Bg;

    for (int s = 0; s < 128; s++) {
        const int buf = s & 1;

        // ---- store staged slab (A duplicated, B scalar) ----
        {
            float* ab = sA + buf * ABUF + ks * RSA + 2 * row;
            *(u64*)(ab + 0 * RSA) = pack_dup(ra.x);
            *(u64*)(ab + 1 * RSA) = pack_dup(ra.y);
            *(u64*)(ab + 2 * RSA) = pack_dup(ra.z);
            *(u64*)(ab + 3 * RSA) = pack_dup(ra.w);
            float* bb = sB + buf * BBUF + ks * RSB + row;
            bb[0 * RSB] = rb.x;
            bb[1 * RSB] = rb.y;
            bb[2 * RSB] = rb.z;
            bb[3 * RSB] = rb.w;
        }
        __syncthreads();

        // ---- prefetch next slab ----
        if (s + 1 < 128) {
            const int k0 = (s + 1) * 8;
            ra = *(const float4*)(Ag + k0);
            rb = *(const float4*)(Bg + k0);
        }

        // ---- compute 8 kk ----
        const float* ca = sA + buf * ABUF + 16 * ty;
        const float* cb = sB + buf * BBUF + 4 * tx;
        #pragma unroll
        for (int kk = 0; kk < 8; kk++) {
            ulonglong2 a01 = *(const ulonglong2*)(ca + kk * RSA);
            ulonglong2 a23 = *(const ulonglong2*)(ca + kk * RSA + 4);
            ulonglong2 a45 = *(const ulonglong2*)(ca + kk * RSA + 8);
            ulonglong2 a67 = *(const ulonglong2*)(ca + kk * RSA + 12);
            ulonglong2 b01 = *(const ulonglong2*)(cb + kk * RSB);
            ulonglong2 b23 = *(const ulonglong2*)(cb + kk * RSB + 64);
            u64 ad[8] = { a01.x, a01.y, a23.x, a23.y,
                          a45.x, a45.y, a67.x, a67.y };
            u64 bv[4] = { b01.x, b01.y, b23.x, b23.y };
            #pragma unroll
            for (int i = 0; i < 8; i++)
                #pragma unroll
                for (int j = 0; j < 4; j++)
                    fma2(acc[i][j], ad[i], bv[j]);
        }
    }

    // ---- epilogue ----
    const int cb0 = n0 + 4 * tx;        // group 0 cols
    const int cb1 = cb0 + 64;           // group 1 cols
    float4 bn0, bn1;
    if (epi == 0) {
        bn0 = *(const float4*)(aux + cb0);
        bn1 = *(const float4*)(aux + cb1);
    }
    #pragma unroll
    for (int i = 0; i < 8; i++) {
        const int r = m0 + 8 * ty + i;
        float2 f0 = *reinterpret_cast<float2*>(&acc[i][0]);
        float2 f1 = *reinterpret_cast<float2*>(&acc[i][1]);
        float2 f2 = *reinterpret_cast<float2*>(&acc[i][2]);
        float2 f3 = *reinterpret_cast<float2*>(&acc[i][3]);
        float4 v0 = make_float4(f0.x, f0.y, f1.x, f1.y);
        float4 v1 = make_float4(f2.x, f2.y, f3.x, f3.y);
        if (epi == 0) {
            v0.x += bn0.x; v0.y += bn0.y; v0.z += bn0.z; v0.w += bn0.w;
            v1.x += bn1.x; v1.y += bn1.y; v1.z += bn1.z; v1.w += bn1.w;
        } else if (epi == 1) {
            const float bm = aux[r];
            v0.x += bm; v0.y += bm; v0.z += bm; v0.w += bm;
            v1.x += bm; v1.y += bm; v1.z += bm; v1.w += bm;
        } else if (epi == 2) {
            const float4 d0 = *(const float4*)(aux + (size_t)r * ldC + cb0);
            const float4 d1 = *(const float4*)(aux + (size_t)r * ldC + cb1);
            v0.x /= d0.x; v0.y /= d0.y; v0.z /= d0.z; v0.w /= d0.w;
            v1.x /= d1.x; v1.y /= d1.y; v1.z /= d1.z; v1.w /= d1.w;
        }
        *(float4*)(C + (size_t)r * ldC + cb0) = v0;
        *(float4*)(C + (size_t)r * ldC + cb1) = v1;
    }
}

// ---------------------------------------------------------------------------
// Fused kernel: the 4 independent linears in one grid (1536 CTAs).
//   [0,256)     k   = y @ W2^T + b2      M=4096, N=1024: 32 x 8 tiles
//   [256,512)   vT  = W3 @ y^T + b3[m]   M=1024, N=4096: 8 x 32, ldC=4096
//   [512,1024)  qy  = x @ W4^T + b4      M=8192, N=1024: 64 x 8
//   [1024,1536) inv = x @ W5^T + b5      M=8192, N=1024: 64 x 8
// ---------------------------------------------------------------------------
__global__ void __launch_bounds__(256, 2) k_fused(
    const float* __restrict__ x, const float* __restrict__ y,
    const float* __restrict__ W2, const float* __restrict__ b2,
    const float* __restrict__ W3, const float* __restrict__ b3,
    const float* __restrict__ W4, const float* __restrict__ b4,
    const float* __restrict__ W5, const float* __restrict__ b5,
    float* __restrict__ gk, float* __restrict__ gvt,
    float* __restrict__ gqy, float* __restrict__ ginv)
{
    __shared__ __align__(16) float sA[2 * ABUF];
    __shared__ __align__(16) float sB[2 * BBUF];

    const int t = blockIdx.x;
    const float *A, *B, *aux;
    float* C;
    int ldC, epi, m0, n0;

    if (t < 256) {
        A = y;  B = W2; C = gk;   aux = b2; ldC = 1024; epi = 0;
        m0 = (t >> 3) << 7; n0 = (t & 7) << 7;
    } else if (t < 512) {
        const int u = t - 256;
        A = W3; B = y;  C = gvt;  aux = b3; ldC = 4096; epi = 1;
        m0 = (u >> 5) << 7; n0 = (u & 31) << 7;
    } else if (t < 1024) {
        const int u = t - 512;
        A = x;  B = W4; C = gqy;  aux = b4; ldC = 1024; epi = 0;
        m0 = (u >> 3) << 7; n0 = (u & 7) << 7;
    } else {
        const int u = t - 1024;
        A = x;  B = W5; C = ginv; aux = b5; ldC = 1024; epi = 0;
        m0 = (u >> 3) << 7; n0 = (u & 7) << 7;
    }
    run_gemm(A, 1024, B, 1024, C, ldC, aux, epi, m0, n0, sA, sB);
}

// qk = (qy @ k^T) / inv, per batch z
__global__ void __launch_bounds__(256, 2) k_qk(
    const float* __restrict__ gqy, const float* __restrict__ gk,
    const float* __restrict__ ginv, float* __restrict__ gqk)
{
    __shared__ __align__(16) float sA[2 * ABUF];
    __shared__ __align__(16) float sB[2 * BBUF];
    const size_t z = blockIdx.z;
    run_gemm(gqy + z * (2048ull * 1024), 1024,
             gk  + z * (1024ull * 1024), 1024,
             gqk + z * (2048ull * 1024), 1024,
             ginv + z * (2048ull * 1024), 2,
             blockIdx.y * 128, blockIdx.x * 128, sA, sB);
}

// out = attn @ vT^T, per batch z (B row n lives at gvt + z*1024 + n*4096)
__global__ void __launch_bounds__(256, 2) k_av(
    const float* __restrict__ gqk, const float* __restrict__ gvt,
    float* __restrict__ out)
{
    __shared__ __align__(16) float sA[2 * ABUF];
    __shared__ __align__(16) float sB[2 * BBUF];
    const size_t z = blockIdx.z;
    run_gemm(gqk + z * (2048ull * 1024), 1024,
             gvt + z * 1024, 4096,
             out + z * (2048ull * 1024), 1024,
             nullptr, 3,
             blockIdx.y * 128, blockIdx.x * 128, sA, sB);
}

// ---------------------------------------------------------------------------
// Row softmax over 1024, in place. 1 block/row, 256 threads. (validated)
// ---------------------------------------------------------------------------
__global__ void __launch_bounds__(256) softmax1024(float* __restrict__ data)
{
    float* p = data + (size_t)blockIdx.x * 1024;
    const int t = threadIdx.x, lane = t & 31, warp = t >> 5;
    __shared__ float red[8];
    __shared__ float stat[2];

    float4 x = *((const float4*)p + t);
    float m = fmaxf(fmaxf(x.x, x.y), fmaxf(x.z, x.w));
    #pragma unroll
    for (int o = 16; o > 0; o >>= 1) m = fmaxf(m, __shfl_xor_sync(~0u, m, o));
    if (lane == 0) red[warp] = m;
    __syncthreads();
    if (t == 0) {
        float mm = red[0];
        #pragma unroll
        for (int i = 1; i < 8; i++) mm = fmaxf(mm, red[i]);
        stat[0] = mm;
    }
    __syncthreads();
    const float bm = stat[0];
    x.x = __expf(x.x - bm); x.y = __expf(x.y - bm);
    x.z = __expf(x.z - bm); x.w = __expf(x.w - bm);
    float s = (x.x + x.y) + (x.z + x.w);
    #pragma unroll
    for (int o = 16; o > 0; o >>= 1) s += __shfl_xor_sync(~0u, s, o);
    __syncthreads();
    if (lane == 0) red[warp] = s;
    __syncthreads();
    if (t == 0) {
        float ss = red[0];
        #pragma unroll
        for (int i = 1; i < 8; i++) ss += red[i];
        stat[1] = 1.0f / ss;
    }
    __syncthreads();
    const float r = stat[1];
    x.x *= r; x.y *= r; x.z *= r; x.w *= r;
    *((float4*)p + t) = x;
}

// ---------------------------------------------------------------------------
static float* symaddr(const void* s) {
    void* p = nullptr;
    cudaGetSymbolAddress(&p, s);
    return (float*)p;
}

extern "C" void kernel_launch(void* const* d_in, const int* in_sizes, int n_in,
                              void* d_out, int out_size)
{
    (void)in_sizes; (void)n_in; (void)out_size;
    const float* x  = (const float*)d_in[0];
    const float* y  = (const float*)d_in[1];
    const float* W2 = (const float*)d_in[4];  const float* b2 = (const float*)d_in[5];
    const float* W3 = (const float*)d_in[6];  const float* b3 = (const float*)d_in[7];
    const float* W4 = (const float*)d_in[8];  const float* b4 = (const float*)d_in[9];
    const float* W5 = (const float*)d_in[10]; const float* b5 = (const float*)d_in[11];
    float* out = (float*)d_out;

    float* gk   = symaddr(g_k);
    float* gvt  = symaddr(g_vt);
    float* gqy  = symaddr(g_qy);
    float* ginv = symaddr(g_inv);
    float* gqk  = symaddr(g_qk);

    // 1) four independent linears, one launch (1536 tiles of 128x128)
    k_fused<<<1536, 256>>>(x, y, W2, b2, W3, b3, W4, b4, W5, b5,
                           gk, gvt, gqy, ginv);

    // 2) qk = (qy @ k^T) / inv   (8 x 16 x 4 tiles)
    k_qk<<<dim3(8, 16, 4), 256>>>(gqy, gk, ginv, gqk);

    // 3) softmax rows (in place)
    softmax1024<<<8192, 256>>>(gqk);

    // 4) out = attn @ v          (8 x 16 x 4 tiles)
    k_av<<<dim3(8, 16, 4), 256>>>(gqk, gvt, out);
}